// round 16
// baseline (speedup 1.0000x reference)
#include <cuda_runtime.h>
#include <cuda_fp16.h>
#include <cstdint>

// ---------------- problem constants ----------------
#define D_    64
#define HW_   4096
#define K_    512
#define NPTS  131072
#define NELEM 8388608LL

#define MTPB   512
#define MGRID  148
#define NTILES (NPTS / 128)   // 1024

// ---- main smem byte offsets (A/B tiles 1024-aligned for SW128) ----
#define SM_Y     0        // 512 f32 (y + 0.5, screen)
#define SM_YE    2048     // 512 f32 (exact y)
#define SM_BKF   4096     // 128 int
#define SM_FLAG  4608     // 128 int
#define SM_RED   5120     // 32 f32
#define SM_K1S   5248     // 256 u32
#define SM_K2S   6272     // 256 u32
#define SM_K3S   7296     // 256 u32
#define SM_K4S   8320     // 256 u32
#define SM_PX    9344     // 4*128 f32
#define SM_BMAX  11392    // 2 f32 (El, Bmax)
#define SM_AHI   12288    // 128*128 B fp16 z (SW128)
#define SM_BH    28672    // 512*128 B fp16 cb (SW128)
#define SMEM_TOTAL 94208

// fallback smem: padded fp32 codebook [512][65] + exact y
#define FB_SMEM (K_ * 65 * 4 + K_ * 4)   // 135168 B
#define FB_CTAS 148
#define FB_TPB  512

// ---------------- device globals (zero-init; fallback resets) ----------------
__device__ double g_loss_accum;
__device__ int    g_cnt_full;
__device__ int    g_done;
__device__ int    g_wl_full[NPTS];
__device__ float  g_y[K_];            // EXACT sequential sum e_i^2

#define SWZ128(off) ((off) ^ (((off) >> 3) & 0x70))

__device__ __forceinline__ uint32_t smem_u32_of(const void* p) {
    uint32_t a;
    asm("{ .reg .u64 t; cvta.to.shared.u64 t, %1; cvt.u32.u64 %0, t; }"
        : "=r"(a) : "l"(p));
    return a;
}
__device__ __forceinline__ void mma_f16(float* c, const uint32_t* a,
                                        uint32_t b0, uint32_t b1) {
    asm volatile(
        "mma.sync.aligned.m16n8k16.row.col.f32.f16.f16.f32 "
        "{%0,%1,%2,%3}, {%4,%5,%6,%7}, {%8,%9}, {%0,%1,%2,%3};"
        : "+f"(c[0]), "+f"(c[1]), "+f"(c[2]), "+f"(c[3])
        : "r"(a[0]), "r"(a[1]), "r"(a[2]), "r"(a[3]), "r"(b0), "r"(b1));
}
__device__ __forceinline__ void ldsm_x4(uint32_t* r, uint32_t addr) {
    asm volatile(
        "ldmatrix.sync.aligned.m8n8.x4.shared.b16 {%0,%1,%2,%3}, [%4];"
        : "=r"(r[0]), "=r"(r[1]), "=r"(r[2]), "=r"(r[3]) : "r"(addr));
}
__device__ __forceinline__ uint32_t pack_f16x2(float lo, float hi) {
    __half2 h = __floats2half2_rn(lo, hi);
    return *reinterpret_cast<uint32_t*>(&h);
}
// key = (fbits(t) & ~0x1FF) | k ; t > 0 -> monotone; ties -> smaller k.
__device__ __forceinline__ uint32_t mkkey(float t, int k) {
    return (__float_as_uint(t) & 0xFFFFFE00u) | (uint32_t)k;
}
// Insert key into sorted top-4 (branchless).
__device__ __forceinline__ void upd4(uint32_t key, uint32_t& k1, uint32_t& k2,
                                     uint32_t& k3, uint32_t& k4) {
    k4 = min(k4, max(k3, key));
    k3 = min(k3, max(k2, key));
    k2 = min(k2, max(k1, key));
    k1 = min(k1, key);
}

// ---------------- main: persistent, 1-pass fp16 screen + 4-tier ----------------
__global__ __launch_bounds__(MTPB, 1)
void vq_main_kernel(const float* __restrict__ z,
                    const float* __restrict__ cb,
                    float* __restrict__ out) {
    extern __shared__ char smem[];
    const uint32_t smb = smem_u32_of(smem);
    float*    s_y    = (float*)(smem + SM_Y);
    float*    s_ye   = (float*)(smem + SM_YE);
    int*      s_bkf  = (int*)(smem + SM_BKF);
    int*      s_flag = (int*)(smem + SM_FLAG);
    float*    s_red  = (float*)(smem + SM_RED);
    uint32_t* s_k1s  = (uint32_t*)(smem + SM_K1S);
    uint32_t* s_k2s  = (uint32_t*)(smem + SM_K2S);
    uint32_t* s_k3s  = (uint32_t*)(smem + SM_K3S);
    uint32_t* s_k4s  = (uint32_t*)(smem + SM_K4S);
    float*    s_px   = (float*)(smem + SM_PX);
    float*    s_bmax = (float*)(smem + SM_BMAX);

    const int tid  = threadIdx.x;
    const int wid  = tid >> 5;
    const int lane = tid & 31;
    const int g    = lane >> 2;
    const int tg   = lane & 3;
    const int p    = tid & 127;
    const int q4   = tid >> 7;

    // ---- stage B once: exact y; fp16 tile; exact max ||e-fp16(e)||, max ||e|| ----
    {
        const int k = tid;        // 0..511
        const float4* e4 = (const float4*)(cb + k * D_);
        float ev[D_];
        #pragma unroll
        for (int i = 0; i < 16; i++) {
            float4 v = __ldg(e4 + i);
            ev[4*i] = v.x; ev[4*i+1] = v.y; ev[4*i+2] = v.z; ev[4*i+3] = v.w;
        }
        float s = 0.f;
        #pragma unroll
        for (int i = 0; i < D_; i++) s = __fadd_rn(s, __fmul_rn(ev[i], ev[i]));
        if (blockIdx.x == 0) g_y[k] = s;
        s_ye[k] = s;
        s_y[k]  = s + 0.5f;
        float elsq = 0.f;
        #pragma unroll
        for (int j = 0; j < 32; j++) {
            float v0 = ev[2*j], v1 = ev[2*j+1];
            float h0 = __half2float(__float2half_rn(v0));
            float h1 = __half2float(__float2half_rn(v1));
            float l0 = v0 - h0, l1 = v1 - h1;
            elsq = fmaf(l0, l0, fmaf(l1, l1, elsq));
            uint32_t off = (uint32_t)(k * 128 + j * 4);
            *(uint32_t*)(smem + SM_BH + SWZ128(off)) = pack_f16x2(v0, v1);
        }
        float ymax = s;
        #pragma unroll
        for (int off = 16; off > 0; off >>= 1) {
            elsq = fmaxf(elsq, __shfl_xor_sync(0xffffffffu, elsq, off));
            ymax = fmaxf(ymax, __shfl_xor_sync(0xffffffffu, ymax, off));
        }
        if (lane == 0) { s_red[wid] = elsq; s_red[16 + wid] = ymax; }
    }
    __syncthreads();
    if (tid == 0) {
        float m = 0.f, ym = 0.f;
        #pragma unroll
        for (int i = 0; i < 16; i++) {
            m  = fmaxf(m,  s_red[i]);
            ym = fmaxf(ym, s_red[16 + i]);
        }
        s_bmax[0] = sqrtf(m) * 1.001f;    // El
        s_bmax[1] = sqrtf(ym) * 1.001f;   // Bmax = max ||e||
    }
    __syncthreads();
    // per-point window factor: 2.2 * (El + 2^-11 * Bmax)
    const float Wfac = 2.2f * (s_bmax[0] + 4.8828125e-4f * s_bmax[1]);

    const int row0 = (wid >> 1) * 16 + g;
    const int nh   = wid & 1;
    const int lr = lane & 7;
    const int ms = lane >> 3;
    const uint32_t colx0 = (uint32_t)((ms * 16) ^ (lr << 4));
    const uint32_t colx1 = (uint32_t)((64 + ms * 16) ^ (lr << 4));
    const uint32_t browz = (uint32_t)((nh * 256 + lr) * 128);

    for (int tile = blockIdx.x; tile < NTILES; tile += gridDim.x) {
        const int base = tile * 128;
        const int b    = base >> 12;
        const int hw0  = base & (HW_ - 1);
        const float* zb = z + (size_t)b * D_ * HW_ + hw0;

        // ---- stage A: z -> fp16 tile; ||z||^2 partials ----
        {
            const int c0s = q4 * 16;
            float px = 0.f;
            #pragma unroll
            for (int j = 0; j < 8; j++) {
                int c = c0s + 2 * j;
                float v0 = __ldg(zb + (size_t)c * HW_ + p);
                float v1 = __ldg(zb + (size_t)(c + 1) * HW_ + p);
                px = fmaf(v0, v0, fmaf(v1, v1, px));
                uint32_t off = (uint32_t)(p * 128 + c * 2);
                *(uint32_t*)(smem + SM_AHI + SWZ128(off)) = pack_f16x2(v0, v1);
            }
            s_px[q4 * 128 + p] = px;
        }
        __syncthreads();

        // ---- A fragments (validated layout) ----
        uint32_t ah[4][4];
        #pragma unroll
        for (int ks = 0; ks < 4; ks++) {
            uint32_t o = (uint32_t)(row0 * 128 + ks * 32 + tg * 4);
            ah[ks][0] = *(uint32_t*)(smem + SM_AHI + SWZ128(o));
            ah[ks][1] = *(uint32_t*)(smem + SM_AHI + SWZ128(o + 8 * 128));
            ah[ks][2] = *(uint32_t*)(smem + SM_AHI + SWZ128(o + 16));
            ah[ks][3] = *(uint32_t*)(smem + SM_AHI + SWZ128(o + 8 * 128 + 16));
        }

        uint32_t bh0 = smb + SM_BH + browz + colx0;
        uint32_t bh1 = smb + SM_BH + browz + colx1;

        uint32_t k1a = 0xFFFFFFFFu, k2a = 0xFFFFFFFFu;
        uint32_t k3a = 0xFFFFFFFFu, k4a = 0xFFFFFFFFu;
        uint32_t k1b = 0xFFFFFFFFu, k2b = 0xFFFFFFFFu;
        uint32_t k3b = 0xFFFFFFFFu, k4b = 0xFFFFFFFFu;

        #pragma unroll 4
        for (int nb = 0; nb < 32; nb++) {
            uint32_t h1[4], h2[4];
            ldsm_x4(h1, bh0); ldsm_x4(h2, bh1);
            bh0 += 1024; bh1 += 1024;

            float acc[4] = {0.f, 0.f, 0.f, 0.f};
            mma_f16(acc, ah[0], h1[0], h1[1]);
            mma_f16(acc, ah[1], h1[2], h1[3]);
            mma_f16(acc, ah[2], h2[0], h2[1]);
            mma_f16(acc, ah[3], h2[2], h2[3]);

            const int c0 = nh * 256 + nb * 8 + tg * 2;
            float2 y2 = *(const float2*)&s_y[c0];       // y + 0.5
            float t0 = fmaf(-2.f, acc[0], y2.x);        // > 0
            float t1 = fmaf(-2.f, acc[1], y2.y);
            float t2 = fmaf(-2.f, acc[2], y2.x);
            float t3 = fmaf(-2.f, acc[3], y2.y);
            upd4(mkkey(t0, c0),     k1a, k2a, k3a, k4a);
            upd4(mkkey(t1, c0 + 1), k1a, k2a, k3a, k4a);
            upd4(mkkey(t2, c0),     k1b, k2b, k3b, k4b);
            upd4(mkkey(t3, c0 + 1), k1b, k2b, k3b, k4b);
        }

        // quad merge (tg bits): top-4 on u32 keys
        #pragma unroll
        for (int off = 1; off <= 2; off <<= 1) {
            uint32_t n1 = __shfl_xor_sync(0xffffffffu, k1a, off);
            uint32_t n2 = __shfl_xor_sync(0xffffffffu, k2a, off);
            uint32_t n3 = __shfl_xor_sync(0xffffffffu, k3a, off);
            uint32_t n4 = __shfl_xor_sync(0xffffffffu, k4a, off);
            upd4(n1, k1a, k2a, k3a, k4a); upd4(n2, k1a, k2a, k3a, k4a);
            upd4(n3, k1a, k2a, k3a, k4a); upd4(n4, k1a, k2a, k3a, k4a);
            n1 = __shfl_xor_sync(0xffffffffu, k1b, off);
            n2 = __shfl_xor_sync(0xffffffffu, k2b, off);
            n3 = __shfl_xor_sync(0xffffffffu, k3b, off);
            n4 = __shfl_xor_sync(0xffffffffu, k4b, off);
            upd4(n1, k1b, k2b, k3b, k4b); upd4(n2, k1b, k2b, k3b, k4b);
            upd4(n3, k1b, k2b, k3b, k4b); upd4(n4, k1b, k2b, k3b, k4b);
        }
        if (tg == 0) {
            s_k1s[row0 * 2 + nh] = k1a; s_k2s[row0 * 2 + nh] = k2a;
            s_k3s[row0 * 2 + nh] = k3a; s_k4s[row0 * 2 + nh] = k4a;
            s_k1s[(row0 + 8) * 2 + nh] = k1b; s_k2s[(row0 + 8) * 2 + nh] = k2b;
            s_k3s[(row0 + 8) * 2 + nh] = k3b; s_k4s[(row0 + 8) * 2 + nh] = k4b;
        }
        __syncthreads();

        // ---- decision: winner / inline-pair / inline-trio / full worklist ----
        if (tid < 128) {
            uint32_t a1 = s_k1s[tid * 2], a2 = s_k2s[tid * 2];
            uint32_t a3 = s_k3s[tid * 2], a4 = s_k4s[tid * 2];
            upd4(s_k1s[tid*2+1], a1, a2, a3, a4);
            upd4(s_k2s[tid*2+1], a1, a2, a3, a4);
            upd4(s_k3s[tid*2+1], a1, a2, a3, a4);
            upd4(s_k4s[tid*2+1], a1, a2, a3, a4);
            float f1 = __uint_as_float(a1 & 0xFFFFFE00u);
            float f2 = __uint_as_float(a2 & 0xFFFFFE00u);
            float f3 = __uint_as_float(a3 & 0xFFFFFE00u);
            float f4 = __uint_as_float(a4 & 0xFFFFFE00u);
            float px = s_px[tid] + s_px[128 + tid]
                     + s_px[256 + tid] + s_px[384 + tid];
            float gridw = (px < 63.7f) ? 1.7e-5f : (px < 127.7f ? 3.3e-5f : 6.6e-5f);
            float W = gridw + 4.4e-5f + Wfac * sqrtf(px);
            if (f2 - f1 >= W) {
                s_bkf[tid] = (int)(a1 & 511u); s_flag[tid] = 0;
            } else if (f3 - f1 >= W) {
                // exactly 2 candidates: resolve inline, bit-exact
                const int c1 = (int)(a1 & 511u), c2 = (int)(a2 & 511u);
                const float4* e1r = (const float4*)(cb + c1 * D_);
                const float4* e2r = (const float4*)(cb + c2 * D_);
                float x = 0.f, m1 = 0.f, m2 = 0.f;
                #pragma unroll
                for (int i = 0; i < 16; i++) {
                    float z0 = __ldg(zb + (size_t)(4*i+0) * HW_ + tid);
                    float z1 = __ldg(zb + (size_t)(4*i+1) * HW_ + tid);
                    float z2 = __ldg(zb + (size_t)(4*i+2) * HW_ + tid);
                    float z3 = __ldg(zb + (size_t)(4*i+3) * HW_ + tid);
                    float4 e1 = __ldg(e1r + i);
                    float4 e2 = __ldg(e2r + i);
                    x = __fadd_rn(x, __fmul_rn(z0, z0));
                    x = __fadd_rn(x, __fmul_rn(z1, z1));
                    x = __fadd_rn(x, __fmul_rn(z2, z2));
                    x = __fadd_rn(x, __fmul_rn(z3, z3));
                    m1 = __fmaf_rn(z0, e1.x, m1); m2 = __fmaf_rn(z0, e2.x, m2);
                    m1 = __fmaf_rn(z1, e1.y, m1); m2 = __fmaf_rn(z1, e2.y, m2);
                    m1 = __fmaf_rn(z2, e1.z, m1); m2 = __fmaf_rn(z2, e2.z, m2);
                    m1 = __fmaf_rn(z3, e1.w, m1); m2 = __fmaf_rn(z3, e2.w, m2);
                }
                float d1 = __fadd_rn(__fadd_rn(x, s_ye[c1]), -__fmul_rn(2.f, m1));
                float d2 = __fadd_rn(__fadd_rn(x, s_ye[c2]), -__fmul_rn(2.f, m2));
                int bk = (d1 < d2 || (d1 == d2 && c1 < c2)) ? c1 : c2;
                s_bkf[tid] = bk; s_flag[tid] = 0;
            } else if (f4 - f1 >= W) {
                // exactly 3 candidates: resolve inline, bit-exact
                const int c1 = (int)(a1 & 511u), c2 = (int)(a2 & 511u);
                const int c3 = (int)(a3 & 511u);
                const float4* e1r = (const float4*)(cb + c1 * D_);
                const float4* e2r = (const float4*)(cb + c2 * D_);
                const float4* e3r = (const float4*)(cb + c3 * D_);
                float x = 0.f, m1 = 0.f, m2 = 0.f, m3 = 0.f;
                #pragma unroll
                for (int i = 0; i < 16; i++) {
                    float z0 = __ldg(zb + (size_t)(4*i+0) * HW_ + tid);
                    float z1 = __ldg(zb + (size_t)(4*i+1) * HW_ + tid);
                    float z2 = __ldg(zb + (size_t)(4*i+2) * HW_ + tid);
                    float z3 = __ldg(zb + (size_t)(4*i+3) * HW_ + tid);
                    float4 e1 = __ldg(e1r + i);
                    float4 e2 = __ldg(e2r + i);
                    float4 e3 = __ldg(e3r + i);
                    x = __fadd_rn(x, __fmul_rn(z0, z0));
                    x = __fadd_rn(x, __fmul_rn(z1, z1));
                    x = __fadd_rn(x, __fmul_rn(z2, z2));
                    x = __fadd_rn(x, __fmul_rn(z3, z3));
                    m1 = __fmaf_rn(z0, e1.x, m1); m2 = __fmaf_rn(z0, e2.x, m2);
                    m3 = __fmaf_rn(z0, e3.x, m3);
                    m1 = __fmaf_rn(z1, e1.y, m1); m2 = __fmaf_rn(z1, e2.y, m2);
                    m3 = __fmaf_rn(z1, e3.y, m3);
                    m1 = __fmaf_rn(z2, e1.z, m1); m2 = __fmaf_rn(z2, e2.z, m2);
                    m3 = __fmaf_rn(z2, e3.z, m3);
                    m1 = __fmaf_rn(z3, e1.w, m1); m2 = __fmaf_rn(z3, e2.w, m2);
                    m3 = __fmaf_rn(z3, e3.w, m3);
                }
                float d1 = __fadd_rn(__fadd_rn(x, s_ye[c1]), -__fmul_rn(2.f, m1));
                float d2 = __fadd_rn(__fadd_rn(x, s_ye[c2]), -__fmul_rn(2.f, m2));
                float d3 = __fadd_rn(__fadd_rn(x, s_ye[c3]), -__fmul_rn(2.f, m3));
                int bk; float bd;
                if (d1 < d2 || (d1 == d2 && c1 < c2)) { bd = d1; bk = c1; }
                else                                   { bd = d2; bk = c2; }
                if (d3 < bd || (d3 == bd && c3 < bk))  { bk = c3; }
                s_bkf[tid] = bk; s_flag[tid] = 0;
            } else {
                s_flag[tid] = 1;
                int i = atomicAdd(&g_cnt_full, 1);
                g_wl_full[i] = base + tid;
            }
        }
        __syncthreads();

        // ---- output + loss for resolved points ----
        float lsum = 0.f;
        if (!s_flag[p]) {
            const int bestk = s_bkf[p];
            const float4* e4 = (const float4*)(cb + bestk * D_);
            float* op = out + (size_t)b * D_ * HW_ + hw0 + p;
            #pragma unroll
            for (int j4 = 0; j4 < 4; j4++) {
                float4 e = __ldg(e4 + q4 * 4 + j4);
                #pragma unroll
                for (int u = 0; u < 4; u++) {
                    int c = q4 * 16 + 4 * j4 + u;
                    float qq = (u == 0) ? e.x : (u == 1) ? e.y : (u == 2) ? e.z : e.w;
                    float zv = __ldg(zb + (size_t)c * HW_ + p);
                    float dd = __fadd_rn(qq, -zv);
                    lsum = __fmaf_rn(dd, dd, lsum);
                    op[(size_t)c * HW_] = __fadd_rn(zv, dd);
                }
            }
        }
        #pragma unroll
        for (int off = 16; off > 0; off >>= 1)
            lsum += __shfl_down_sync(0xffffffffu, lsum, off);
        if (lane == 0) s_red[wid] = lsum;
        __syncthreads();
        if (tid == 0) {
            float v = 0.f;
            #pragma unroll
            for (int i = 0; i < 16; i++) v += s_red[i];
            atomicAdd(&g_loss_accum, (double)v);
        }
        __syncthreads();
    }
}

// ---------------- fallback: full-tier scans (512 thr) + fused finalize ----------------
__global__ __launch_bounds__(FB_TPB, 1)
void vq_fallback_kernel(const float* __restrict__ z,
                        const float* __restrict__ cb,
                        float* __restrict__ out, int loss_idx) {
    extern __shared__ float fsm[];
    float* s_cb = fsm;               // [512][65] padded fp32
    float* s_ye = fsm + K_ * 65;     // exact y

    const int tid  = threadIdx.x;
    const int lane = tid & 31;
    const int wid  = tid >> 5;
    const int cnt  = g_cnt_full;

    if (cnt > 0) {
        // stage padded codebook + exact y
        for (int idx = tid; idx < K_ * D_; idx += FB_TPB) {
            int k = idx >> 6, i = idx & 63;
            s_cb[k * 65 + i] = __ldg(cb + idx);
        }
        for (int i = tid; i < K_; i += FB_TPB) s_ye[i] = g_y[i];
        __syncthreads();

        float ls_tot = 0.f;
        const int gw = blockIdx.x * (FB_TPB / 32) + wid;
        const int nw = FB_CTAS * (FB_TPB / 32);
        for (int w = gw; w < cnt; w += nw) {
            const int n  = g_wl_full[w];
            const int b  = n >> 12;
            const int hw = n & (HW_ - 1);
            const float* zp = z + (size_t)b * D_ * HW_ + hw;

            float zv[D_];
            #pragma unroll
            for (int i = 0; i < D_; i++) zv[i] = __ldg(zp + (size_t)i * HW_);
            float x = 0.f;
            #pragma unroll
            for (int i = 0; i < D_; i++) x = __fadd_rn(x, __fmul_rn(zv[i], zv[i]));

            // lane handles codes lane + 32*j (conflict-free banks), 4-ILP
            float bd = 3.4e38f; int bk = K_;
            #pragma unroll 1
            for (int j4 = 0; j4 < 4; j4++) {
                const int kbase = lane + j4 * 128;
                const float* r0 = s_cb + (kbase +  0) * 65;
                const float* r1 = s_cb + (kbase + 32) * 65;
                const float* r2 = s_cb + (kbase + 64) * 65;
                const float* r3 = s_cb + (kbase + 96) * 65;
                float a0 = 0.f, a1 = 0.f, a2 = 0.f, a3 = 0.f;
                #pragma unroll
                for (int i = 0; i < D_; i++) {
                    float zi = zv[i];
                    a0 = __fmaf_rn(zi, r0[i], a0);
                    a1 = __fmaf_rn(zi, r1[i], a1);
                    a2 = __fmaf_rn(zi, r2[i], a2);
                    a3 = __fmaf_rn(zi, r3[i], a3);
                }
                float d0 = __fadd_rn(__fadd_rn(x, s_ye[kbase +  0]), -__fmul_rn(2.f, a0));
                float d1 = __fadd_rn(__fadd_rn(x, s_ye[kbase + 32]), -__fmul_rn(2.f, a1));
                float d2 = __fadd_rn(__fadd_rn(x, s_ye[kbase + 64]), -__fmul_rn(2.f, a2));
                float d3 = __fadd_rn(__fadd_rn(x, s_ye[kbase + 96]), -__fmul_rn(2.f, a3));
                if (d0 < bd || (d0 == bd && kbase      < bk)) { bd = d0; bk = kbase; }
                if (d1 < bd || (d1 == bd && kbase + 32 < bk)) { bd = d1; bk = kbase + 32; }
                if (d2 < bd || (d2 == bd && kbase + 64 < bk)) { bd = d2; bk = kbase + 64; }
                if (d3 < bd || (d3 == bd && kbase + 96 < bk)) { bd = d3; bk = kbase + 96; }
            }
            // lexicographic (d, k) min across lanes => first-index tie rule
            #pragma unroll
            for (int off = 16; off > 0; off >>= 1) {
                float od = __shfl_down_sync(0xffffffffu, bd, off);
                int   ok = __shfl_down_sync(0xffffffffu, bk, off);
                if (od < bd || (od == bd && ok < bk)) { bd = od; bk = ok; }
            }
            bk = __shfl_sync(0xffffffffu, bk, 0);

            float* op = out + (size_t)b * D_ * HW_ + hw;
            const float* e = s_cb + bk * 65;
            #pragma unroll
            for (int h = 0; h < 2; h++) {
                int c = lane + 32 * h;
                float dd = __fadd_rn(e[c], -zv[c]);
                ls_tot = __fmaf_rn(dd, dd, ls_tot);
                op[(size_t)c * HW_] = __fadd_rn(zv[c], dd);
            }
        }
        #pragma unroll
        for (int off = 16; off > 0; off >>= 1)
            ls_tot += __shfl_down_sync(0xffffffffu, ls_tot, off);
        if (lane == 0 && ls_tot != 0.f)
            atomicAdd(&g_loss_accum, (double)ls_tot);
    }

    // fused finalize: last CTA writes loss + resets state for graph replays
    __syncthreads();
    if (tid == 0) {
        __threadfence();
        int old = atomicAdd(&g_done, 1);
        if (old == FB_CTAS - 1) {
            double lv = atomicAdd(&g_loss_accum, 0.0);
            out[loss_idx] = (float)(lv * 1.25 / (double)NELEM);
            g_loss_accum = 0.0;
            g_cnt_full = 0;
            g_done = 0;
            __threadfence();
        }
    }
}

extern "C" void kernel_launch(void* const* d_in, const int* in_sizes, int n_in,
                              void* d_out, int out_size) {
    const float* z  = (const float*)d_in[0];
    const float* cb = (const float*)d_in[1];
    float* out = (float*)d_out;

    static bool attr_set = false;
    if (!attr_set) {
        cudaFuncSetAttribute(vq_main_kernel,
                             cudaFuncAttributeMaxDynamicSharedMemorySize,
                             SMEM_TOTAL);
        cudaFuncSetAttribute(vq_fallback_kernel,
                             cudaFuncAttributeMaxDynamicSharedMemorySize,
                             FB_SMEM);
        attr_set = true;
    }

    vq_main_kernel<<<MGRID, MTPB, SMEM_TOTAL>>>(z, cb, out);
    vq_fallback_kernel<<<FB_CTAS, FB_TPB, FB_SMEM>>>(z, cb, out, out_size - 1);
}

// round 17
// speedup vs baseline: 1.0381x; 1.0381x over previous
#include <cuda_runtime.h>
#include <cuda_fp16.h>
#include <cstdint>

// ---------------- problem constants ----------------
#define D_    64
#define HW_   4096
#define K_    512
#define NPTS  131072
#define NELEM 8388608LL

#define MTPB   512
#define MGRID  148
#define NTILES (NPTS / 128)   // 1024

// ---- main smem byte offsets (A/B tiles 1024-aligned for SW128) ----
#define SM_Y     0        // 512 f32 (y + 0.5, screen)
#define SM_YE    2048     // 512 f32 (exact y)
#define SM_BKF   4096     // 128 int
#define SM_FLAG  4608     // 128 int
#define SM_RED   5120     // 32 f32
#define SM_K1S   5248     // 256 u32
#define SM_K2S   6272     // 256 u32
#define SM_K3S   7296     // 256 u32
#define SM_PX    8320     // 4*128 f32
#define SM_BMAX  10368    // 2 f32 (El, Bmax)
#define SM_AHI   12288    // 128*128 B fp16 z (SW128)
#define SM_BH    28672    // 512*128 B fp16 cb (SW128)
#define SMEM_TOTAL 94208

// fallback smem: padded fp32 codebook [512][65] + exact y
#define FB_SMEM (K_ * 65 * 4 + K_ * 4)   // 135168 B
#define FB_CTAS 148
#define FB_TPB  512

// ---------------- device globals (zero-init; fallback resets) ----------------
__device__ double g_loss_accum;
__device__ int    g_cnt_full;
__device__ int    g_done;
__device__ int    g_wl_full[NPTS];
__device__ float  g_y[K_];            // EXACT sequential sum e_i^2

#define SWZ128(off) ((off) ^ (((off) >> 3) & 0x70))

__device__ __forceinline__ uint32_t smem_u32_of(const void* p) {
    uint32_t a;
    asm("{ .reg .u64 t; cvta.to.shared.u64 t, %1; cvt.u32.u64 %0, t; }"
        : "=r"(a) : "l"(p));
    return a;
}
__device__ __forceinline__ void mma_f16(float* c, const uint32_t* a,
                                        uint32_t b0, uint32_t b1) {
    asm volatile(
        "mma.sync.aligned.m16n8k16.row.col.f32.f16.f16.f32 "
        "{%0,%1,%2,%3}, {%4,%5,%6,%7}, {%8,%9}, {%0,%1,%2,%3};"
        : "+f"(c[0]), "+f"(c[1]), "+f"(c[2]), "+f"(c[3])
        : "r"(a[0]), "r"(a[1]), "r"(a[2]), "r"(a[3]), "r"(b0), "r"(b1));
}
__device__ __forceinline__ void ldsm_x4(uint32_t* r, uint32_t addr) {
    asm volatile(
        "ldmatrix.sync.aligned.m8n8.x4.shared.b16 {%0,%1,%2,%3}, [%4];"
        : "=r"(r[0]), "=r"(r[1]), "=r"(r[2]), "=r"(r[3]) : "r"(addr));
}
__device__ __forceinline__ uint32_t pack_f16x2(float lo, float hi) {
    __half2 h = __floats2half2_rn(lo, hi);
    return *reinterpret_cast<uint32_t*>(&h);
}
// key = (fbits(t) & ~0x1FF) | k ; t > 0 -> monotone; ties -> smaller k.
__device__ __forceinline__ uint32_t mkkey(float t, int k) {
    return (__float_as_uint(t) & 0xFFFFFE00u) | (uint32_t)k;
}
// Insert key into sorted top-3 (branchless).
__device__ __forceinline__ void upd3(uint32_t key, uint32_t& k1,
                                     uint32_t& k2, uint32_t& k3) {
    k3 = min(k3, max(k2, key));
    k2 = min(k2, max(k1, key));
    k1 = min(k1, key);
}

// ---------------- main: persistent, 1-pass fp16 screen + 3-tier (R14) ----------------
__global__ __launch_bounds__(MTPB, 1)
void vq_main_kernel(const float* __restrict__ z,
                    const float* __restrict__ cb,
                    float* __restrict__ out) {
    extern __shared__ char smem[];
    const uint32_t smb = smem_u32_of(smem);
    float*    s_y    = (float*)(smem + SM_Y);
    float*    s_ye   = (float*)(smem + SM_YE);
    int*      s_bkf  = (int*)(smem + SM_BKF);
    int*      s_flag = (int*)(smem + SM_FLAG);
    float*    s_red  = (float*)(smem + SM_RED);
    uint32_t* s_k1s  = (uint32_t*)(smem + SM_K1S);
    uint32_t* s_k2s  = (uint32_t*)(smem + SM_K2S);
    uint32_t* s_k3s  = (uint32_t*)(smem + SM_K3S);
    float*    s_px   = (float*)(smem + SM_PX);
    float*    s_bmax = (float*)(smem + SM_BMAX);

    const int tid  = threadIdx.x;
    const int wid  = tid >> 5;
    const int lane = tid & 31;
    const int g    = lane >> 2;
    const int tg   = lane & 3;
    const int p    = tid & 127;
    const int q4   = tid >> 7;

    // ---- stage B once: exact y; fp16 tile; exact max ||e-fp16(e)||, max ||e|| ----
    {
        const int k = tid;        // 0..511
        const float4* e4 = (const float4*)(cb + k * D_);
        float ev[D_];
        #pragma unroll
        for (int i = 0; i < 16; i++) {
            float4 v = __ldg(e4 + i);
            ev[4*i] = v.x; ev[4*i+1] = v.y; ev[4*i+2] = v.z; ev[4*i+3] = v.w;
        }
        float s = 0.f;
        #pragma unroll
        for (int i = 0; i < D_; i++) s = __fadd_rn(s, __fmul_rn(ev[i], ev[i]));
        if (blockIdx.x == 0) g_y[k] = s;
        s_ye[k] = s;
        s_y[k]  = s + 0.5f;
        float elsq = 0.f;
        #pragma unroll
        for (int j = 0; j < 32; j++) {
            float v0 = ev[2*j], v1 = ev[2*j+1];
            float h0 = __half2float(__float2half_rn(v0));
            float h1 = __half2float(__float2half_rn(v1));
            float l0 = v0 - h0, l1 = v1 - h1;
            elsq = fmaf(l0, l0, fmaf(l1, l1, elsq));
            uint32_t off = (uint32_t)(k * 128 + j * 4);
            *(uint32_t*)(smem + SM_BH + SWZ128(off)) = pack_f16x2(v0, v1);
        }
        float ymax = s;
        #pragma unroll
        for (int off = 16; off > 0; off >>= 1) {
            elsq = fmaxf(elsq, __shfl_xor_sync(0xffffffffu, elsq, off));
            ymax = fmaxf(ymax, __shfl_xor_sync(0xffffffffu, ymax, off));
        }
        if (lane == 0) { s_red[wid] = elsq; s_red[16 + wid] = ymax; }
    }
    __syncthreads();
    if (tid == 0) {
        float m = 0.f, ym = 0.f;
        #pragma unroll
        for (int i = 0; i < 16; i++) {
            m  = fmaxf(m,  s_red[i]);
            ym = fmaxf(ym, s_red[16 + i]);
        }
        s_bmax[0] = sqrtf(m) * 1.001f;    // El
        s_bmax[1] = sqrtf(ym) * 1.001f;   // Bmax = max ||e||
    }
    __syncthreads();
    // per-point window factor: 2.2 * (El + 2^-11 * Bmax)
    const float Wfac = 2.2f * (s_bmax[0] + 4.8828125e-4f * s_bmax[1]);

    const int row0 = (wid >> 1) * 16 + g;
    const int nh   = wid & 1;
    const int lr = lane & 7;
    const int ms = lane >> 3;
    const uint32_t colx0 = (uint32_t)((ms * 16) ^ (lr << 4));
    const uint32_t colx1 = (uint32_t)((64 + ms * 16) ^ (lr << 4));
    const uint32_t browz = (uint32_t)((nh * 256 + lr) * 128);

    for (int tile = blockIdx.x; tile < NTILES; tile += gridDim.x) {
        const int base = tile * 128;
        const int b    = base >> 12;
        const int hw0  = base & (HW_ - 1);
        const float* zb = z + (size_t)b * D_ * HW_ + hw0;

        // ---- stage A: z -> fp16 tile; ||z||^2 partials ----
        {
            const int c0s = q4 * 16;
            float px = 0.f;
            #pragma unroll
            for (int j = 0; j < 8; j++) {
                int c = c0s + 2 * j;
                float v0 = __ldg(zb + (size_t)c * HW_ + p);
                float v1 = __ldg(zb + (size_t)(c + 1) * HW_ + p);
                px = fmaf(v0, v0, fmaf(v1, v1, px));
                uint32_t off = (uint32_t)(p * 128 + c * 2);
                *(uint32_t*)(smem + SM_AHI + SWZ128(off)) = pack_f16x2(v0, v1);
            }
            s_px[q4 * 128 + p] = px;
        }
        __syncthreads();

        // ---- A fragments (validated layout) ----
        uint32_t ah[4][4];
        #pragma unroll
        for (int ks = 0; ks < 4; ks++) {
            uint32_t o = (uint32_t)(row0 * 128 + ks * 32 + tg * 4);
            ah[ks][0] = *(uint32_t*)(smem + SM_AHI + SWZ128(o));
            ah[ks][1] = *(uint32_t*)(smem + SM_AHI + SWZ128(o + 8 * 128));
            ah[ks][2] = *(uint32_t*)(smem + SM_AHI + SWZ128(o + 16));
            ah[ks][3] = *(uint32_t*)(smem + SM_AHI + SWZ128(o + 8 * 128 + 16));
        }

        uint32_t bh0 = smb + SM_BH + browz + colx0;
        uint32_t bh1 = smb + SM_BH + browz + colx1;

        uint32_t k1a = 0xFFFFFFFFu, k2a = 0xFFFFFFFFu, k3a = 0xFFFFFFFFu;
        uint32_t k1b = 0xFFFFFFFFu, k2b = 0xFFFFFFFFu, k3b = 0xFFFFFFFFu;

        #pragma unroll 4
        for (int nb = 0; nb < 32; nb++) {
            uint32_t h1[4], h2[4];
            ldsm_x4(h1, bh0); ldsm_x4(h2, bh1);
            bh0 += 1024; bh1 += 1024;

            float acc[4] = {0.f, 0.f, 0.f, 0.f};
            mma_f16(acc, ah[0], h1[0], h1[1]);
            mma_f16(acc, ah[1], h1[2], h1[3]);
            mma_f16(acc, ah[2], h2[0], h2[1]);
            mma_f16(acc, ah[3], h2[2], h2[3]);

            const int c0 = nh * 256 + nb * 8 + tg * 2;
            float2 y2 = *(const float2*)&s_y[c0];       // y + 0.5
            float t0 = fmaf(-2.f, acc[0], y2.x);        // > 0
            float t1 = fmaf(-2.f, acc[1], y2.y);
            float t2 = fmaf(-2.f, acc[2], y2.x);
            float t3 = fmaf(-2.f, acc[3], y2.y);
            upd3(mkkey(t0, c0),     k1a, k2a, k3a);
            upd3(mkkey(t1, c0 + 1), k1a, k2a, k3a);
            upd3(mkkey(t2, c0),     k1b, k2b, k3b);
            upd3(mkkey(t3, c0 + 1), k1b, k2b, k3b);
        }

        // quad merge (tg bits): top-3 on u32 keys
        #pragma unroll
        for (int off = 1; off <= 2; off <<= 1) {
            uint32_t n1 = __shfl_xor_sync(0xffffffffu, k1a, off);
            uint32_t n2 = __shfl_xor_sync(0xffffffffu, k2a, off);
            uint32_t n3 = __shfl_xor_sync(0xffffffffu, k3a, off);
            upd3(n1, k1a, k2a, k3a); upd3(n2, k1a, k2a, k3a);
            upd3(n3, k1a, k2a, k3a);
            n1 = __shfl_xor_sync(0xffffffffu, k1b, off);
            n2 = __shfl_xor_sync(0xffffffffu, k2b, off);
            n3 = __shfl_xor_sync(0xffffffffu, k3b, off);
            upd3(n1, k1b, k2b, k3b); upd3(n2, k1b, k2b, k3b);
            upd3(n3, k1b, k2b, k3b);
        }
        if (tg == 0) {
            s_k1s[row0 * 2 + nh] = k1a; s_k2s[row0 * 2 + nh] = k2a;
            s_k3s[row0 * 2 + nh] = k3a;
            s_k1s[(row0 + 8) * 2 + nh] = k1b; s_k2s[(row0 + 8) * 2 + nh] = k2b;
            s_k3s[(row0 + 8) * 2 + nh] = k3b;
        }
        __syncthreads();

        // ---- decision: merge halves; winner / inline-pair / full worklist ----
        if (tid < 128) {
            uint32_t a1 = s_k1s[tid * 2], a2 = s_k2s[tid * 2], a3 = s_k3s[tid * 2];
            upd3(s_k1s[tid*2+1], a1, a2, a3);
            upd3(s_k2s[tid*2+1], a1, a2, a3);
            upd3(s_k3s[tid*2+1], a1, a2, a3);
            float f1 = __uint_as_float(a1 & 0xFFFFFE00u);
            float f2 = __uint_as_float(a2 & 0xFFFFFE00u);
            float f3 = __uint_as_float(a3 & 0xFFFFFE00u);
            float px = s_px[tid] + s_px[128 + tid]
                     + s_px[256 + tid] + s_px[384 + tid];
            float gridw = (px < 63.7f) ? 1.7e-5f : (px < 127.7f ? 3.3e-5f : 6.6e-5f);
            float W = gridw + 4.4e-5f + Wfac * sqrtf(px);
            if (f2 - f1 >= W) {
                s_bkf[tid] = (int)(a1 & 511u); s_flag[tid] = 0;
            } else if (f3 - f1 >= W) {
                // exactly 2 candidates: resolve inline, bit-exact
                const int c1 = (int)(a1 & 511u), c2 = (int)(a2 & 511u);
                const float4* e1r = (const float4*)(cb + c1 * D_);
                const float4* e2r = (const float4*)(cb + c2 * D_);
                float x = 0.f, m1 = 0.f, m2 = 0.f;
                #pragma unroll
                for (int i = 0; i < 16; i++) {
                    float z0 = __ldg(zb + (size_t)(4*i+0) * HW_ + tid);
                    float z1 = __ldg(zb + (size_t)(4*i+1) * HW_ + tid);
                    float z2 = __ldg(zb + (size_t)(4*i+2) * HW_ + tid);
                    float z3 = __ldg(zb + (size_t)(4*i+3) * HW_ + tid);
                    float4 e1 = __ldg(e1r + i);
                    float4 e2 = __ldg(e2r + i);
                    x = __fadd_rn(x, __fmul_rn(z0, z0));
                    x = __fadd_rn(x, __fmul_rn(z1, z1));
                    x = __fadd_rn(x, __fmul_rn(z2, z2));
                    x = __fadd_rn(x, __fmul_rn(z3, z3));
                    m1 = __fmaf_rn(z0, e1.x, m1); m2 = __fmaf_rn(z0, e2.x, m2);
                    m1 = __fmaf_rn(z1, e1.y, m1); m2 = __fmaf_rn(z1, e2.y, m2);
                    m1 = __fmaf_rn(z2, e1.z, m1); m2 = __fmaf_rn(z2, e2.z, m2);
                    m1 = __fmaf_rn(z3, e1.w, m1); m2 = __fmaf_rn(z3, e2.w, m2);
                }
                float d1 = __fadd_rn(__fadd_rn(x, s_ye[c1]), -__fmul_rn(2.f, m1));
                float d2 = __fadd_rn(__fadd_rn(x, s_ye[c2]), -__fmul_rn(2.f, m2));
                int bk = (d1 < d2 || (d1 == d2 && c1 < c2)) ? c1 : c2;
                s_bkf[tid] = bk; s_flag[tid] = 0;
            } else {
                s_flag[tid] = 1;
                int i = atomicAdd(&g_cnt_full, 1);
                g_wl_full[i] = base + tid;
            }
        }
        __syncthreads();

        // ---- output + loss for resolved points ----
        float lsum = 0.f;
        if (!s_flag[p]) {
            const int bestk = s_bkf[p];
            const float4* e4 = (const float4*)(cb + bestk * D_);
            float* op = out + (size_t)b * D_ * HW_ + hw0 + p;
            #pragma unroll
            for (int j4 = 0; j4 < 4; j4++) {
                float4 e = __ldg(e4 + q4 * 4 + j4);
                #pragma unroll
                for (int u = 0; u < 4; u++) {
                    int c = q4 * 16 + 4 * j4 + u;
                    float qq = (u == 0) ? e.x : (u == 1) ? e.y : (u == 2) ? e.z : e.w;
                    float zv = __ldg(zb + (size_t)c * HW_ + p);
                    float dd = __fadd_rn(qq, -zv);
                    lsum = __fmaf_rn(dd, dd, lsum);
                    op[(size_t)c * HW_] = __fadd_rn(zv, dd);
                }
            }
        }
        #pragma unroll
        for (int off = 16; off > 0; off >>= 1)
            lsum += __shfl_down_sync(0xffffffffu, lsum, off);
        if (lane == 0) s_red[wid] = lsum;
        __syncthreads();
        if (tid == 0) {
            float v = 0.f;
            #pragma unroll
            for (int i = 0; i < 16; i++) v += s_red[i];
            atomicAdd(&g_loss_accum, (double)v);
        }
        __syncthreads();
    }
}

// ---------------- fallback: full-tier scans (512 thr) + fused finalize ----------------
__global__ __launch_bounds__(FB_TPB, 1)
void vq_fallback_kernel(const float* __restrict__ z,
                        const float* __restrict__ cb,
                        float* __restrict__ out, int loss_idx) {
    extern __shared__ float fsm[];
    float* s_cb = fsm;               // [512][65] padded fp32
    float* s_ye = fsm + K_ * 65;     // exact y

    const int tid  = threadIdx.x;
    const int lane = tid & 31;
    const int wid  = tid >> 5;
    const int cnt  = g_cnt_full;

    if (cnt > 0) {
        // stage padded codebook + exact y
        for (int idx = tid; idx < K_ * D_; idx += FB_TPB) {
            int k = idx >> 6, i = idx & 63;
            s_cb[k * 65 + i] = __ldg(cb + idx);
        }
        for (int i = tid; i < K_; i += FB_TPB) s_ye[i] = g_y[i];
        __syncthreads();

        float ls_tot = 0.f;
        const int gw = blockIdx.x * (FB_TPB / 32) + wid;
        const int nw = FB_CTAS * (FB_TPB / 32);
        for (int w = gw; w < cnt; w += nw) {
            const int n  = g_wl_full[w];
            const int b  = n >> 12;
            const int hw = n & (HW_ - 1);
            const float* zp = z + (size_t)b * D_ * HW_ + hw;

            float zv[D_];
            #pragma unroll
            for (int i = 0; i < D_; i++) zv[i] = __ldg(zp + (size_t)i * HW_);
            float x = 0.f;
            #pragma unroll
            for (int i = 0; i < D_; i++) x = __fadd_rn(x, __fmul_rn(zv[i], zv[i]));

            // lane handles codes lane + 32*j (conflict-free banks), 4-ILP
            float bd = 3.4e38f; int bk = K_;
            #pragma unroll 1
            for (int j4 = 0; j4 < 4; j4++) {
                const int kbase = lane + j4 * 128;
                const float* r0 = s_cb + (kbase +  0) * 65;
                const float* r1 = s_cb + (kbase + 32) * 65;
                const float* r2 = s_cb + (kbase + 64) * 65;
                const float* r3 = s_cb + (kbase + 96) * 65;
                float a0 = 0.f, a1 = 0.f, a2 = 0.f, a3 = 0.f;
                #pragma unroll
                for (int i = 0; i < D_; i++) {
                    float zi = zv[i];
                    a0 = __fmaf_rn(zi, r0[i], a0);
                    a1 = __fmaf_rn(zi, r1[i], a1);
                    a2 = __fmaf_rn(zi, r2[i], a2);
                    a3 = __fmaf_rn(zi, r3[i], a3);
                }
                float d0 = __fadd_rn(__fadd_rn(x, s_ye[kbase +  0]), -__fmul_rn(2.f, a0));
                float d1 = __fadd_rn(__fadd_rn(x, s_ye[kbase + 32]), -__fmul_rn(2.f, a1));
                float d2 = __fadd_rn(__fadd_rn(x, s_ye[kbase + 64]), -__fmul_rn(2.f, a2));
                float d3 = __fadd_rn(__fadd_rn(x, s_ye[kbase + 96]), -__fmul_rn(2.f, a3));
                if (d0 < bd || (d0 == bd && kbase      < bk)) { bd = d0; bk = kbase; }
                if (d1 < bd || (d1 == bd && kbase + 32 < bk)) { bd = d1; bk = kbase + 32; }
                if (d2 < bd || (d2 == bd && kbase + 64 < bk)) { bd = d2; bk = kbase + 64; }
                if (d3 < bd || (d3 == bd && kbase + 96 < bk)) { bd = d3; bk = kbase + 96; }
            }
            // lexicographic (d, k) min across lanes => first-index tie rule
            #pragma unroll
            for (int off = 16; off > 0; off >>= 1) {
                float od = __shfl_down_sync(0xffffffffu, bd, off);
                int   ok = __shfl_down_sync(0xffffffffu, bk, off);
                if (od < bd || (od == bd && ok < bk)) { bd = od; bk = ok; }
            }
            bk = __shfl_sync(0xffffffffu, bk, 0);

            float* op = out + (size_t)b * D_ * HW_ + hw;
            const float* e = s_cb + bk * 65;
            #pragma unroll
            for (int h = 0; h < 2; h++) {
                int c = lane + 32 * h;
                float dd = __fadd_rn(e[c], -zv[c]);
                ls_tot = __fmaf_rn(dd, dd, ls_tot);
                op[(size_t)c * HW_] = __fadd_rn(zv[c], dd);
            }
        }
        #pragma unroll
        for (int off = 16; off > 0; off >>= 1)
            ls_tot += __shfl_down_sync(0xffffffffu, ls_tot, off);
        if (lane == 0 && ls_tot != 0.f)
            atomicAdd(&g_loss_accum, (double)ls_tot);
    }

    // fused finalize: last CTA writes loss + resets state for graph replays
    __syncthreads();
    if (tid == 0) {
        __threadfence();
        int old = atomicAdd(&g_done, 1);
        if (old == FB_CTAS - 1) {
            double lv = atomicAdd(&g_loss_accum, 0.0);
            out[loss_idx] = (float)(lv * 1.25 / (double)NELEM);
            g_loss_accum = 0.0;
            g_cnt_full = 0;
            g_done = 0;
            __threadfence();
        }
    }
}

extern "C" void kernel_launch(void* const* d_in, const int* in_sizes, int n_in,
                              void* d_out, int out_size) {
    const float* z  = (const float*)d_in[0];
    const float* cb = (const float*)d_in[1];
    float* out = (float*)d_out;

    static bool attr_set = false;
    if (!attr_set) {
        cudaFuncSetAttribute(vq_main_kernel,
                             cudaFuncAttributeMaxDynamicSharedMemorySize,
                             SMEM_TOTAL);
        cudaFuncSetAttribute(vq_fallback_kernel,
                             cudaFuncAttributeMaxDynamicSharedMemorySize,
                             FB_SMEM);
        attr_set = true;
    }

    vq_main_kernel<<<MGRID, MTPB, SMEM_TOTAL>>>(z, cb, out);
    vq_fallback_kernel<<<FB_CTAS, FB_TPB, FB_SMEM>>>(z, cb, out, out_size - 1);
}